// round 6
// baseline (speedup 1.0000x reference)
#include <cuda_runtime.h>
#include <cuda_fp16.h>
#include <cstdint>
#include <math.h>

// Problem dims (fixed)
#define BATCH 2048
#define TT    20
#define CD    512
#define HD    1024
#define VD    2048
#define QD    1024

// ---------------- fp32 scratch -------------------------------------------------
__device__ float g_fv   [BATCH * CD];
__device__ float g_fq   [BATCH * CD];
__device__ float g_fvq  [BATCH * CD];
__device__ float g_gi1a [BATCH * TT * 3 * CD];            // gate-interleaved
__device__ float g_gi2a [(size_t)BATCH * TT * 3 * HD];    // gate-interleaved
__device__ float g_h1   [BATCH * CD];
__device__ float g_h2   [BATCH * HD];
__device__ float g_y    [(size_t)BATCH * TT * HD];
__device__ float g_bih1p[3 * CD];
__device__ float g_bhh1p[3 * CD];
__device__ float g_bih2p[3 * HD];
__device__ float g_bhh2p[3 * HD];

// ---------------- fp16 scratch -------------------------------------------------
__device__ __half g_c16  [BATCH * TT * CD];
__device__ __half g_v16  [BATCH * VD];
__device__ __half g_q16  [BATCH * QD];
__device__ __half g_wih1p[3 * CD * CD];   // permuted gate-interleaved
__device__ __half g_whh1p[3 * CD * CD];
__device__ __half g_wih2p[3 * HD * CD];
__device__ __half g_whh2p[3 * HD * HD];
__device__ __half g_wvh  [CD * VD];
__device__ __half g_wqh  [CD * QD];
__device__ __half g_wfch [HD * HD];
__device__ __half g_h1h  [BATCH * CD];
__device__ __half g_h2h  [BATCH * HD];
__device__ __half g_atta [BATCH * TT * CD];
__device__ __half g_h2ah [(size_t)BATCH * TT * HD];

// ---------------- helpers --------------------------------------------------------
__device__ __forceinline__ float sigmf(float x) { return 1.0f / (1.0f + expf(-x)); }
__device__ __forceinline__ float leakyf(float x) { return x > 0.0f ? x : 0.01f * x; }

__device__ __forceinline__ void mma_f16(
    float& c0, float& c1, float& c2, float& c3,
    uint32_t a0, uint32_t a1, uint32_t a2, uint32_t a3,
    uint32_t b0, uint32_t b1)
{
    asm volatile(
        "mma.sync.aligned.m16n8k16.row.col.f32.f16.f16.f32 "
        "{%0,%1,%2,%3}, {%4,%5,%6,%7}, {%8,%9}, {%0,%1,%2,%3};"
        : "+f"(c0), "+f"(c1), "+f"(c2), "+f"(c3)
        : "r"(a0), "r"(a1), "r"(a2), "r"(a3), "r"(b0), "r"(b1));
}

__device__ __forceinline__ void ldm_x4(uint32_t& r0, uint32_t& r1, uint32_t& r2, uint32_t& r3,
                                       uint32_t saddr)
{
    asm volatile("ldmatrix.sync.aligned.m8n8.x4.shared.b16 {%0,%1,%2,%3}, [%4];"
                 : "=r"(r0), "=r"(r1), "=r"(r2), "=r"(r3) : "r"(saddr));
}

__device__ __forceinline__ void cp16(uint32_t saddr, const void* gptr) {
    asm volatile("cp.async.cg.shared.global [%0], [%1], 16;" :: "r"(saddr), "l"(gptr));
}
__device__ __forceinline__ void cp_commit() { asm volatile("cp.async.commit_group;"); }
__device__ __forceinline__ void cp_wait1()  { asm volatile("cp.async.wait_group 1;"); }

// ================= plain fp16 GEMM (validated R5 engine) ========================
// C[M,N] = A[M,K]h @ B[N,K]h^T (+bias fp32, +leaky). 128x128 tile, K-chunk 32.
#define LDSH 40
#define TILEB (128 * LDSH * 2)
#define STAGEB_P (2 * TILEB)
#define SMEM_P (3 * STAGEB_P)

__global__ __launch_bounds__(256, 2) void h16_gemm_nt(
    const __half* __restrict__ A, const __half* __restrict__ B,
    const float* __restrict__ bias, float* __restrict__ C,
    int M, int N, int K, int epi)
{
    extern __shared__ __align__(16) char smem[];
    const int tid  = threadIdx.x;
    const int wid  = tid >> 5;
    const int lane = tid & 31;
    const int wm   = wid >> 1;
    const int wn   = wid & 1;
    const int g    = lane >> 2;
    const int t    = lane & 3;
    const int bm = blockIdx.y * 128;
    const int bn = blockIdx.x * 128;

    const __half* Ag = A + (size_t)bm * K;
    const __half* Bg = B + (size_t)bn * K;
    const uint32_t sbase = (uint32_t)__cvta_generic_to_shared(smem);

    const int r0s = tid >> 2, v0s = tid & 3;
    const int r1s = (tid + 256) >> 2, v1s = tid & 3;

    const uint32_t a_off = (uint32_t)(((lane & 15) * LDSH + (lane >> 4) * 8) * 2);
    const int b_row = ((lane >> 4) << 3) + (lane & 7);
    const uint32_t b_koff = (uint32_t)((((lane >> 3) & 1) * 8) * 2);

    float acc[2][8][4];
#pragma unroll
    for (int i = 0; i < 2; i++)
#pragma unroll
        for (int j = 0; j < 8; j++)
#pragma unroll
            for (int r = 0; r < 4; r++) acc[i][j][r] = 0.0f;

    const int NKC = K >> 5;

    auto issue = [&](int kc) {
        const int st = kc % 3;
        const uint32_t sa = sbase + st * STAGEB_P;
        const uint32_t sb = sa + TILEB;
        const uint32_t o0 = (uint32_t)((r0s * LDSH + v0s * 8) * 2);
        const uint32_t o1 = (uint32_t)((r1s * LDSH + v1s * 8) * 2);
        cp16(sa + o0, Ag + (size_t)r0s * K + kc * 32 + v0s * 8);
        cp16(sb + o0, Bg + (size_t)r0s * K + kc * 32 + v0s * 8);
        cp16(sa + o1, Ag + (size_t)r1s * K + kc * 32 + v1s * 8);
        cp16(sb + o1, Bg + (size_t)r1s * K + kc * 32 + v1s * 8);
        cp_commit();
    };

    issue(0);
    issue(1);

    for (int kc = 0; kc < NKC; kc++) {
        cp_wait1();
        __syncthreads();
        const int st = kc % 3;
        const uint32_t cAb = sbase + st * STAGEB_P;
        const uint32_t cBb = cAb + TILEB;
#pragma unroll
        for (int ks = 0; ks < 2; ks++) {
            const uint32_t kso = (uint32_t)(ks * 16 * 2);
            uint32_t af[2][4];
#pragma unroll
            for (int mt = 0; mt < 2; mt++) {
                const uint32_t addr = cAb + (uint32_t)((wm * 32 + mt * 16) * LDSH * 2)
                                     + a_off + kso;
                ldm_x4(af[mt][0], af[mt][1], af[mt][2], af[mt][3], addr);
            }
            uint32_t bf[8][2];
#pragma unroll
            for (int p = 0; p < 4; p++) {
                const uint32_t addr = cBb
                    + (uint32_t)(((wn * 64 + p * 16 + b_row) * LDSH) * 2)
                    + kso + b_koff;
                ldm_x4(bf[2 * p][0], bf[2 * p][1], bf[2 * p + 1][0], bf[2 * p + 1][1], addr);
            }
#pragma unroll
            for (int mt = 0; mt < 2; mt++)
#pragma unroll
                for (int nt = 0; nt < 8; nt++)
                    mma_f16(acc[mt][nt][0], acc[mt][nt][1],
                            acc[mt][nt][2], acc[mt][nt][3],
                            af[mt][0], af[mt][1], af[mt][2], af[mt][3],
                            bf[nt][0], bf[nt][1]);
        }
        const int nxt = kc + 2;
        if (nxt < NKC) issue(nxt);
    }

#pragma unroll
    for (int mt = 0; mt < 2; mt++) {
        const int r0 = bm + wm * 32 + mt * 16 + g;
#pragma unroll
        for (int nt = 0; nt < 8; nt++) {
            const int col = bn + wn * 64 + nt * 8 + 2 * t;
            float b0 = 0.0f, b1 = 0.0f;
            if (bias) { b0 = bias[col]; b1 = bias[col + 1]; }
            float v0 = acc[mt][nt][0] + b0;
            float v1 = acc[mt][nt][1] + b1;
            float v2 = acc[mt][nt][2] + b0;
            float v3 = acc[mt][nt][3] + b1;
            if (epi == 1) { v0 = leakyf(v0); v1 = leakyf(v1); v2 = leakyf(v2); v3 = leakyf(v3); }
            *(float2*)(C + (size_t)r0 * N + col)       = make_float2(v0, v1);
            *(float2*)(C + (size_t)(r0 + 8) * N + col) = make_float2(v2, v3);
        }
    }
}

// ================= fused recurrent GEMM + GRU cell ===============================
// Per step t: gh = hState16 @ Wg^T (Wg gate-interleaved), then GRU gates in the
// epilogue. CTA(jblk, mb) owns M rows [bm,bm+MT) and all 3 gates of hidden units
// [jblk*128, jblk*128+128). In-place state update is race-free (row ownership).
// MODE 1: GRU1 (+attention, alphas, att_all).  MODE 2: GRU2 (+h2_all).
template<int MT, int F, int MODE>
__global__ __launch_bounds__(512, 1) void fused_gru(
    const __half* __restrict__ Ast,      // state fp16 [BATCH, F]
    const __half* __restrict__ Wg,       // permuted [3F, F]
    const float* __restrict__ bhh,       // permuted [3F]
    const float* __restrict__ giall,     // [BATCH*TT, 3F] gate-interleaved
    const int*   __restrict__ cap_len,
    float* __restrict__ hS, __half* __restrict__ hSh,
    const float* __restrict__ caption,   // MODE1
    const float* __restrict__ fvq,       // MODE1
    __half* __restrict__ attall,         // MODE1
    float* __restrict__ alphas,          // MODE1
    __half* __restrict__ h2ah,           // MODE2
    int t)
{
    constexpr int K   = F;
    constexpr int RT  = MT + 384;
    constexpr int LD  = 72;              // halves per smem row (64 data + 8 pad)
    constexpr int STG = RT * LD * 2;     // bytes per stage
    constexpr int WN  = (MT == 128) ? 4 : 8;
    constexpr int NTN = (MT == 128) ? 4 : 2;
    constexpr int GL  = 3 * F;

    extern __shared__ __align__(16) char smem[];
    const uint32_t sbase = (uint32_t)__cvta_generic_to_shared(smem);

    const int tid  = threadIdx.x;
    const int wid  = tid >> 5;
    const int lane = tid & 31;
    const int wm   = wid / WN;
    const int wn   = wid % WN;
    const int gq   = lane >> 2;
    const int tq   = lane & 3;

    const int jblk = blockIdx.x;
    const int bm   = blockIdx.y * MT;

    const __half* Aw = Ast + (size_t)bm * K;
    const __half* Bw = Wg  + (size_t)jblk * 384 * K;

    const uint32_t a_off  = (uint32_t)(((lane & 15) * LD + (lane >> 4) * 8) * 2);
    const int      b_row  = ((lane >> 4) << 3) + (lane & 7);
    const uint32_t b_koff = (uint32_t)(((lane >> 3) & 1) * 16);

    float acc[3][2][NTN][4];
#pragma unroll
    for (int gg = 0; gg < 3; gg++)
#pragma unroll
        for (int mt = 0; mt < 2; mt++)
#pragma unroll
            for (int nt = 0; nt < NTN; nt++)
#pragma unroll
                for (int r = 0; r < 4; r++) acc[gg][mt][nt][r] = 0.0f;

    auto issue = [&](int kc) {
        const uint32_t s0 = sbase + (uint32_t)((kc % 3) * STG);
#pragma unroll
        for (int s = 0; s < (RT * 8 + 511) / 512; s++) {
            int slot = tid + s * 512;
            if (slot < RT * 8) {
                int row = slot >> 3, v = slot & 7;
                const __half* gp = (row < MT)
                    ? (Aw + (size_t)row * K + kc * 64 + v * 8)
                    : (Bw + (size_t)(row - MT) * K + kc * 64 + v * 8);
                cp16(s0 + (uint32_t)((row * LD + v * 8) * 2), gp);
            }
        }
        cp_commit();
    };

    issue(0);
    issue(1);

    constexpr int NKC = K / 64;
    for (int kc = 0; kc < NKC; kc++) {
        cp_wait1();
        __syncthreads();
        const uint32_t sb = sbase + (uint32_t)((kc % 3) * STG);
#pragma unroll
        for (int ks = 0; ks < 4; ks++) {
            const uint32_t kso = (uint32_t)(ks * 32);
            uint32_t af[2][4];
#pragma unroll
            for (int mt = 0; mt < 2; mt++) {
                const uint32_t addr = sb + (uint32_t)((wm * 32 + mt * 16) * LD * 2)
                                     + a_off + kso;
                ldm_x4(af[mt][0], af[mt][1], af[mt][2], af[mt][3], addr);
            }
#pragma unroll
            for (int gg = 0; gg < 3; gg++) {
                uint32_t bf[NTN][2];
#pragma unroll
                for (int p = 0; p < NTN / 2; p++) {
                    const uint32_t addr = sb
                        + (uint32_t)(((MT + gg * 128 + wn * (NTN * 8) + p * 16 + b_row) * LD) * 2)
                        + kso + b_koff;
                    ldm_x4(bf[2 * p][0], bf[2 * p][1], bf[2 * p + 1][0], bf[2 * p + 1][1], addr);
                }
#pragma unroll
                for (int mt = 0; mt < 2; mt++)
#pragma unroll
                    for (int nt = 0; nt < NTN; nt++)
                        mma_f16(acc[gg][mt][nt][0], acc[gg][mt][nt][1],
                                acc[gg][mt][nt][2], acc[gg][mt][nt][3],
                                af[mt][0], af[mt][1], af[mt][2], af[mt][3],
                                bf[nt][0], bf[nt][1]);
            }
        }
        if (kc + 2 < NKC) issue(kc + 2);
    }

    // -------- fused GRU epilogue --------
#pragma unroll
    for (int mt = 0; mt < 2; mt++) {
#pragma unroll
        for (int rr = 0; rr < 2; rr++) {
            const int row = bm + wm * 32 + mt * 16 + gq + rr * 8;
            const bool active = t < cap_len[row];
            const float* gi = giall + ((size_t)row * TT + t) * GL + jblk * 384;
#pragma unroll
            for (int nt = 0; nt < NTN; nt++) {
                const int cl0 = wn * (NTN * 8) + nt * 8 + 2 * tq;
#pragma unroll
                for (int e = 0; e < 2; e++) {
                    const int cl = cl0 + e;
                    const int j  = jblk * 128 + cl;
                    const int ai = rr * 2 + e;
                    float ghr = acc[0][mt][nt][ai] + bhh[jblk * 384 + cl];
                    float ghz = acc[1][mt][nt][ai] + bhh[jblk * 384 + 128 + cl];
                    float ghn = acc[2][mt][nt][ai] + bhh[jblk * 384 + 256 + cl];
                    float r = sigmf(gi[cl]       + ghr);
                    float z = sigmf(gi[128 + cl] + ghz);
                    float n = tanhf(gi[256 + cl] + r * ghn);
                    float hold = hS[(size_t)row * F + j];
                    float h = active ? ((1.0f - z) * n + z * hold) : hold;
                    hS [(size_t)row * F + j] = h;
                    hSh[(size_t)row * F + j] = __float2half(h);
                    if (MODE == 1) {
                        float x = caption[((size_t)row * TT + t) * F + j];
                        float a = sigmf(h * fvq[(size_t)row * F + j]) * x;
                        attall[((size_t)row * TT + t) * F + j] = __float2half(a);
                        alphas[((size_t)row * TT + t) * F + j] = active ? a : 0.0f;
                    } else {
                        h2ah[((size_t)row * TT + t) * F + j] = __float2half(h);
                    }
                }
            }
        }
    }
}

// ---------------- conversion / misc kernels --------------------------------------
__global__ void f2h_kernel(const float* __restrict__ src, __half* __restrict__ dst, int n) {
    int i = (blockIdx.x * blockDim.x + threadIdx.x) * 4;
    if (i < n) {
        float4 f = *(const float4*)(src + i);
        *(__half2*)(dst + i)     = __floats2half2_rn(f.x, f.y);
        *(__half2*)(dst + i + 2) = __floats2half2_rn(f.z, f.w);
    }
}

// permute weight rows into gate-interleaved order + fp16 convert
__global__ void perm_w_kernel(const float* __restrict__ w, __half* __restrict__ o,
                              int F, int K) {
    int idx = blockIdx.x * blockDim.x + threadIdx.x;
    if (idx >= 3 * F * K) return;
    int c = idx / K, k = idx - c * K;
    int jblk = c / 384, rem = c - jblk * 384;
    int gate = rem >> 7, jj = rem & 127;
    int rw = gate * F + jblk * 128 + jj;
    o[idx] = __float2half(w[(size_t)rw * K + k]);
}

__global__ void perm_b_kernel(const float* __restrict__ b, float* __restrict__ o, int F) {
    int c = blockIdx.x * blockDim.x + threadIdx.x;
    if (c >= 3 * F) return;
    int jblk = c / 384, rem = c - jblk * 384;
    int gate = rem >> 7, jj = rem & 127;
    o[c] = b[gate * F + jblk * 128 + jj];
}

__global__ void zero_state_kernel(float* __restrict__ f, __half* __restrict__ h, int n) {
    int i = blockIdx.x * blockDim.x + threadIdx.x;
    if (i < n) { f[i] = 0.0f; h[i] = __float2half(0.0f); }
}

__global__ void add_kernel(const float* __restrict__ a, const float* __restrict__ b,
                           float* __restrict__ c, int n) {
    int i = blockIdx.x * blockDim.x + threadIdx.x;
    if (i < n) c[i] = a[i] + b[i];
}

__global__ void maxreduce_kernel(
    const float* __restrict__ Y, const int* __restrict__ cap_len, float* __restrict__ out)
{
    int idx = blockIdx.x * blockDim.x + threadIdx.x;
    if (idx >= BATCH * HD) return;
    int b = idx / HD, j = idx - b * HD;
    int len = cap_len[b];
    float m = -INFINITY;
#pragma unroll
    for (int t = 0; t < TT; t++) {
        float v = (t < len) ? leakyf(Y[(size_t)(b * TT + t) * HD + j]) : 0.0f;
        m = fmaxf(m, v);
    }
    out[idx] = m;
}

// ---------------- launch -----------------------------------------------------------
static inline dim3 gemm_grid(int M, int N) { return dim3(N / 128, M / 128); }

extern "C" void kernel_launch(void* const* d_in, const int* in_sizes, int n_in,
                              void* d_out, int out_size)
{
    const float* v       = (const float*)d_in[0];
    const float* q       = (const float*)d_in[1];
    const float* caption = (const float*)d_in[2];
    const int*   cap_len = (const int*)  d_in[3];
    const float* w_ih1   = (const float*)d_in[4];
    const float* w_hh1   = (const float*)d_in[5];
    const float* b_ih1   = (const float*)d_in[6];
    const float* b_hh1   = (const float*)d_in[7];
    const float* w_ih2   = (const float*)d_in[8];
    const float* w_hh2   = (const float*)d_in[9];
    const float* b_ih2   = (const float*)d_in[10];
    const float* b_hh2   = (const float*)d_in[11];
    const float* Wv      = (const float*)d_in[12];
    const float* Wq      = (const float*)d_in[13];
    const float* Wfc     = (const float*)d_in[14];

    float* out    = (float*)d_out;
    float* alphas = (float*)d_out + (size_t)BATCH * HD;

    float *fv, *fq, *fvq, *gi1a, *gi2a, *h1, *h2, *y;
    float *bih1p, *bhh1p, *bih2p, *bhh2p;
    cudaGetSymbolAddress((void**)&fv,    g_fv);
    cudaGetSymbolAddress((void**)&fq,    g_fq);
    cudaGetSymbolAddress((void**)&fvq,   g_fvq);
    cudaGetSymbolAddress((void**)&gi1a,  g_gi1a);
    cudaGetSymbolAddress((void**)&gi2a,  g_gi2a);
    cudaGetSymbolAddress((void**)&h1,    g_h1);
    cudaGetSymbolAddress((void**)&h2,    g_h2);
    cudaGetSymbolAddress((void**)&y,     g_y);
    cudaGetSymbolAddress((void**)&bih1p, g_bih1p);
    cudaGetSymbolAddress((void**)&bhh1p, g_bhh1p);
    cudaGetSymbolAddress((void**)&bih2p, g_bih2p);
    cudaGetSymbolAddress((void**)&bhh2p, g_bhh2p);

    __half *c16, *v16, *q16, *wih1p, *whh1p, *wih2p, *whh2p, *wvh, *wqh, *wfch;
    __half *h1h, *h2h, *atta, *h2ah;
    cudaGetSymbolAddress((void**)&c16,   g_c16);
    cudaGetSymbolAddress((void**)&v16,   g_v16);
    cudaGetSymbolAddress((void**)&q16,   g_q16);
    cudaGetSymbolAddress((void**)&wih1p, g_wih1p);
    cudaGetSymbolAddress((void**)&whh1p, g_whh1p);
    cudaGetSymbolAddress((void**)&wih2p, g_wih2p);
    cudaGetSymbolAddress((void**)&whh2p, g_whh2p);
    cudaGetSymbolAddress((void**)&wvh,   g_wvh);
    cudaGetSymbolAddress((void**)&wqh,   g_wqh);
    cudaGetSymbolAddress((void**)&wfch,  g_wfch);
    cudaGetSymbolAddress((void**)&h1h,   g_h1h);
    cudaGetSymbolAddress((void**)&h2h,   g_h2h);
    cudaGetSymbolAddress((void**)&atta,  g_atta);
    cudaGetSymbolAddress((void**)&h2ah,  g_h2ah);

    // smem attributes
    cudaFuncSetAttribute(h16_gemm_nt, cudaFuncAttributeMaxDynamicSharedMemorySize, SMEM_P);
    const int SM1 = 3 * (64 + 384) * 72 * 2;     // 193536
    const int SM2 = 3 * (128 + 384) * 72 * 2;    // 221184
    cudaFuncSetAttribute(fused_gru<64, CD, 1>,
                         cudaFuncAttributeMaxDynamicSharedMemorySize, SM1);
    cudaFuncSetAttribute(fused_gru<128, HD, 2>,
                         cudaFuncAttributeMaxDynamicSharedMemorySize, SM2);

    const int EW = 256;
    auto cvt = [&](const float* s, __half* d, int n) {
        f2h_kernel<<<(n / 4 + EW - 1) / EW, EW>>>(s, d, n);
    };

    // one-time conversions / permutations
    cvt(caption, c16, BATCH * TT * CD);
    cvt(v,       v16, BATCH * VD);
    cvt(q,       q16, BATCH * QD);
    cvt(Wv,      wvh, CD * VD);
    cvt(Wq,      wqh, CD * QD);
    cvt(Wfc,     wfch, HD * HD);
    perm_w_kernel<<<(3 * CD * CD + EW - 1) / EW, EW>>>(w_ih1, wih1p, CD, CD);
    perm_w_kernel<<<(3 * CD * CD + EW - 1) / EW, EW>>>(w_hh1, whh1p, CD, CD);
    perm_w_kernel<<<(3 * HD * CD + EW - 1) / EW, EW>>>(w_ih2, wih2p, HD, CD);
    perm_w_kernel<<<(3 * HD * HD + EW - 1) / EW, EW>>>(w_hh2, whh2p, HD, HD);
    perm_b_kernel<<<(3 * CD + EW - 1) / EW, EW>>>(b_ih1, bih1p, CD);
    perm_b_kernel<<<(3 * CD + EW - 1) / EW, EW>>>(b_hh1, bhh1p, CD);
    perm_b_kernel<<<(3 * HD + EW - 1) / EW, EW>>>(b_ih2, bih2p, HD);
    perm_b_kernel<<<(3 * HD + EW - 1) / EW, EW>>>(b_hh2, bhh2p, HD);

    // states
    zero_state_kernel<<<(BATCH * CD + EW - 1) / EW, EW>>>(h1, h1h, BATCH * CD);
    zero_state_kernel<<<(BATCH * HD + EW - 1) / EW, EW>>>(h2, h2h, BATCH * HD);

    // hoisted projections (fvq)
    h16_gemm_nt<<<gemm_grid(BATCH, CD), 256, SMEM_P>>>(v16, wvh, nullptr, fv, BATCH, CD, VD, 1);
    h16_gemm_nt<<<gemm_grid(BATCH, CD), 256, SMEM_P>>>(q16, wqh, nullptr, fq, BATCH, CD, QD, 1);
    add_kernel<<<(BATCH * CD + EW - 1) / EW, EW>>>(fv, fq, fvq, BATCH * CD);

    // hoisted GRU1 input GEMM (gate-interleaved output)
    h16_gemm_nt<<<gemm_grid(BATCH * TT, 3 * CD), 256, SMEM_P>>>(
        c16, wih1p, bih1p, gi1a, BATCH * TT, 3 * CD, CD, 0);

    // ---- phase 1: h1 recurrence + attention (writes att_all + alphas) ----
    for (int t = 0; t < TT; t++) {
        fused_gru<64, CD, 1><<<dim3(CD / 128, BATCH / 64), 512, SM1>>>(
            h1h, whh1p, bhh1p, gi1a, cap_len, h1, h1h,
            caption, fvq, atta, alphas, nullptr, t);
    }

    // ---- phase 2: hoisted GRU2 input GEMM over all timesteps ----
    h16_gemm_nt<<<gemm_grid(BATCH * TT, 3 * HD), 256, SMEM_P>>>(
        atta, wih2p, bih2p, gi2a, BATCH * TT, 3 * HD, CD, 0);

    // ---- phase 3: h2 recurrence (writes h2_all) ----
    for (int t = 0; t < TT; t++) {
        fused_gru<128, HD, 2><<<dim3(HD / 128, BATCH / 128), 512, SM2>>>(
            h2h, whh2p, bhh2p, gi2a, cap_len, h2, h2h,
            nullptr, nullptr, nullptr, nullptr, h2ah, t);
    }

    // hoisted output GEMM + masked leaky + time-max
    h16_gemm_nt<<<gemm_grid(BATCH * TT, HD), 256, SMEM_P>>>(
        h2ah, wfch, nullptr, y, BATCH * TT, HD, HD, 0);
    maxreduce_kernel<<<(BATCH * HD + EW - 1) / EW, EW>>>(y, cap_len, out);
}

// round 7
// speedup vs baseline: 1.5378x; 1.5378x over previous
#include <cuda_runtime.h>
#include <cuda_fp16.h>
#include <cstdint>
#include <math.h>

// Problem dims (fixed)
#define BATCH 2048
#define TT    20
#define CD    512
#define HD    1024
#define VD    2048
#define QD    1024

// ---------------- fp32 scratch (rank-sorted / time-major layouts) -------------
__device__ float g_fv   [BATCH * CD];
__device__ float g_fq   [BATCH * CD];
__device__ float g_fvq  [BATCH * CD];                    // sorted
__device__ float g_gi1a [(size_t)TT * BATCH * 3 * CD];   // time-major sorted
__device__ float g_gh1  [BATCH * 3 * CD];
__device__ float g_gi2a [(size_t)TT * BATCH * 3 * HD];   // time-major sorted
__device__ float g_gh2  [BATCH * 3 * HD];
__device__ float g_h1   [BATCH * CD];                    // sorted
__device__ float g_h2   [BATCH * HD];                    // sorted
__device__ float g_y    [(size_t)TT * BATCH * HD];       // time-major sorted

// ---------------- fp16 scratch --------------------------------------------------
__device__ __half g_c16s [(size_t)TT * BATCH * CD];      // caption, time-major sorted
__device__ __half g_v16s [BATCH * VD];                   // sorted rows
__device__ __half g_q16s [BATCH * QD];
__device__ __half g_wih1h[3 * CD * CD];
__device__ __half g_whh1h[3 * CD * CD];
__device__ __half g_wih2h[3 * HD * CD];
__device__ __half g_whh2h[3 * HD * HD];
__device__ __half g_wvh  [CD * VD];
__device__ __half g_wqh  [CD * QD];
__device__ __half g_wfch [HD * HD];
__device__ __half g_h1h  [BATCH * CD];                   // sorted
__device__ __half g_h2h  [BATCH * HD];
__device__ __half g_atta [(size_t)TT * BATCH * CD];      // time-major sorted
__device__ __half g_h2ah [(size_t)TT * BATCH * HD];      // time-major sorted

// ---------------- sorting metadata ----------------------------------------------
__device__ int g_perm [BATCH];   // rank -> orig b
__device__ int g_rank [BATCH];   // orig b -> rank
__device__ int g_mt   [TT];      // active count per step

// ---------------- helpers --------------------------------------------------------
__device__ __forceinline__ float sigmf(float x) { return 1.0f / (1.0f + expf(-x)); }
__device__ __forceinline__ float leakyf(float x) { return x > 0.0f ? x : 0.01f * x; }

__device__ __forceinline__ void mma_f16(
    float& c0, float& c1, float& c2, float& c3,
    uint32_t a0, uint32_t a1, uint32_t a2, uint32_t a3,
    uint32_t b0, uint32_t b1)
{
    asm volatile(
        "mma.sync.aligned.m16n8k16.row.col.f32.f16.f16.f32 "
        "{%0,%1,%2,%3}, {%4,%5,%6,%7}, {%8,%9}, {%0,%1,%2,%3};"
        : "+f"(c0), "+f"(c1), "+f"(c2), "+f"(c3)
        : "r"(a0), "r"(a1), "r"(a2), "r"(a3), "r"(b0), "r"(b1));
}

__device__ __forceinline__ void ldm_x4(uint32_t& r0, uint32_t& r1, uint32_t& r2, uint32_t& r3,
                                       uint32_t saddr)
{
    asm volatile("ldmatrix.sync.aligned.m8n8.x4.shared.b16 {%0,%1,%2,%3}, [%4];"
                 : "=r"(r0), "=r"(r1), "=r"(r2), "=r"(r3) : "r"(saddr));
}

__device__ __forceinline__ void cp16(uint32_t saddr, const void* gptr) {
    asm volatile("cp.async.cg.shared.global [%0], [%1], 16;" :: "r"(saddr), "l"(gptr));
}
__device__ __forceinline__ void cp_commit() { asm volatile("cp.async.commit_group;"); }
__device__ __forceinline__ void cp_wait1()  { asm volatile("cp.async.wait_group 1;"); }

// ================= fp16 GEMM (validated R5 engine + packed early exit) =========
// C[M,N] = A[M,K]h @ B[N,K]h^T (+bias fp32, +leaky).
// mlim: device row-limits. tmaj=1: rows are [t*BATCH + r], CTA exits if
// r0 >= mlim[bm>>11]. tmaj=0: CTA exits if bm >= mlim[tsel].
#define LDSH 40
#define TILEB (128 * LDSH * 2)
#define STAGEB_P (2 * TILEB)
#define SMEM_P (3 * STAGEB_P)

__global__ __launch_bounds__(256, 2) void h16_gemm_nt(
    const __half* __restrict__ A, const __half* __restrict__ B,
    const float* __restrict__ bias, float* __restrict__ C,
    int M, int N, int K, int epi,
    const int* __restrict__ mlim, int tsel, int tmaj)
{
    extern __shared__ __align__(16) char smem[];
    const int bm = blockIdx.y * 128;
    const int bn = blockIdx.x * 128;

    if (mlim) {
        if (tmaj) {
            const int tt = bm >> 11;
            const int r0 = bm & 2047;
            if (r0 >= mlim[tt]) return;
        } else {
            if (bm >= mlim[tsel]) return;
        }
    }

    const int tid  = threadIdx.x;
    const int wid  = tid >> 5;
    const int lane = tid & 31;
    const int wm   = wid >> 1;
    const int wn   = wid & 1;
    const int g    = lane >> 2;
    const int t    = lane & 3;

    const __half* Ag = A + (size_t)bm * K;
    const __half* Bg = B + (size_t)bn * K;
    const uint32_t sbase = (uint32_t)__cvta_generic_to_shared(smem);

    const int r0s = tid >> 2, v0s = tid & 3;
    const int r1s = (tid + 256) >> 2, v1s = tid & 3;

    const uint32_t a_off = (uint32_t)(((lane & 15) * LDSH + (lane >> 4) * 8) * 2);
    const int b_row = ((lane >> 4) << 3) + (lane & 7);
    const uint32_t b_koff = (uint32_t)((((lane >> 3) & 1) * 8) * 2);

    float acc[2][8][4];
#pragma unroll
    for (int i = 0; i < 2; i++)
#pragma unroll
        for (int j = 0; j < 8; j++)
#pragma unroll
            for (int r = 0; r < 4; r++) acc[i][j][r] = 0.0f;

    const int NKC = K >> 5;

    auto issue = [&](int kc) {
        const int st = kc % 3;
        const uint32_t sa = sbase + st * STAGEB_P;
        const uint32_t sb = sa + TILEB;
        const uint32_t o0 = (uint32_t)((r0s * LDSH + v0s * 8) * 2);
        const uint32_t o1 = (uint32_t)((r1s * LDSH + v1s * 8) * 2);
        cp16(sa + o0, Ag + (size_t)r0s * K + kc * 32 + v0s * 8);
        cp16(sb + o0, Bg + (size_t)r0s * K + kc * 32 + v0s * 8);
        cp16(sa + o1, Ag + (size_t)r1s * K + kc * 32 + v1s * 8);
        cp16(sb + o1, Bg + (size_t)r1s * K + kc * 32 + v1s * 8);
        cp_commit();
    };

    issue(0);
    issue(1);

    for (int kc = 0; kc < NKC; kc++) {
        cp_wait1();
        __syncthreads();
        const int st = kc % 3;
        const uint32_t cAb = sbase + st * STAGEB_P;
        const uint32_t cBb = cAb + TILEB;
#pragma unroll
        for (int ks = 0; ks < 2; ks++) {
            const uint32_t kso = (uint32_t)(ks * 16 * 2);
            uint32_t af[2][4];
#pragma unroll
            for (int mt = 0; mt < 2; mt++) {
                const uint32_t addr = cAb + (uint32_t)((wm * 32 + mt * 16) * LDSH * 2)
                                     + a_off + kso;
                ldm_x4(af[mt][0], af[mt][1], af[mt][2], af[mt][3], addr);
            }
            uint32_t bf[8][2];
#pragma unroll
            for (int p = 0; p < 4; p++) {
                const uint32_t addr = cBb
                    + (uint32_t)(((wn * 64 + p * 16 + b_row) * LDSH) * 2)
                    + kso + b_koff;
                ldm_x4(bf[2 * p][0], bf[2 * p][1], bf[2 * p + 1][0], bf[2 * p + 1][1], addr);
            }
#pragma unroll
            for (int mt = 0; mt < 2; mt++)
#pragma unroll
                for (int nt = 0; nt < 8; nt++)
                    mma_f16(acc[mt][nt][0], acc[mt][nt][1],
                            acc[mt][nt][2], acc[mt][nt][3],
                            af[mt][0], af[mt][1], af[mt][2], af[mt][3],
                            bf[nt][0], bf[nt][1]);
        }
        const int nxt = kc + 2;
        if (nxt < NKC) issue(nxt);
    }

#pragma unroll
    for (int mt = 0; mt < 2; mt++) {
        const int r0 = bm + wm * 32 + mt * 16 + g;
#pragma unroll
        for (int nt = 0; nt < 8; nt++) {
            const int col = bn + wn * 64 + nt * 8 + 2 * t;
            float b0 = 0.0f, b1 = 0.0f;
            if (bias) { b0 = bias[col]; b1 = bias[col + 1]; }
            float v0 = acc[mt][nt][0] + b0;
            float v1 = acc[mt][nt][1] + b1;
            float v2 = acc[mt][nt][2] + b0;
            float v3 = acc[mt][nt][3] + b1;
            if (epi == 1) { v0 = leakyf(v0); v1 = leakyf(v1); v2 = leakyf(v2); v3 = leakyf(v3); }
            *(float2*)(C + (size_t)r0 * N + col)       = make_float2(v0, v1);
            *(float2*)(C + (size_t)(r0 + 8) * N + col) = make_float2(v2, v3);
        }
    }
}

// ---------------- sorting / permutation kernels ----------------------------------
// Stable rank by cap_len descending. Deterministic.
__global__ void rank_kernel(const int* __restrict__ len,
                            int* __restrict__ perm, int* __restrict__ rankof)
{
    __shared__ int sl[BATCH];
    const int tid = threadIdx.x;   // 1024
    for (int i = tid; i < BATCH; i += 1024) sl[i] = len[i];
    __syncthreads();
    for (int b = tid; b < BATCH; b += 1024) {
        const int lb = sl[b];
        int rk = 0;
        for (int b2 = 0; b2 < BATCH; b2++) {
            const int l2 = sl[b2];
            rk += (l2 > lb) || (l2 == lb && b2 < b);
        }
        perm[rk] = b;
        rankof[b] = rk;
    }
}

__global__ void mt_kernel(const int* __restrict__ len, int* __restrict__ mt) {
    const int t = threadIdx.x;
    if (t >= TT) return;
    int c = 0;
    for (int b = 0; b < BATCH; b++) c += (len[b] > t);
    mt[t] = c;
}

// plain fp32 -> fp16 (weights)
__global__ void f2h_kernel(const float* __restrict__ src, __half* __restrict__ dst, int n) {
    int i = (blockIdx.x * blockDim.x + threadIdx.x) * 4;
    if (i < n) {
        float4 f = *(const float4*)(src + i);
        *(__half2*)(dst + i)     = __floats2half2_rn(f.x, f.y);
        *(__half2*)(dst + i + 2) = __floats2half2_rn(f.z, f.w);
    }
}

// row-gather fp32 -> fp16 (v, q into sorted order). rowlen % 4 == 0.
__global__ void f2h_perm_kernel(const float* __restrict__ src, __half* __restrict__ dst,
                                const int* __restrict__ perm, int rowlen, int nrows)
{
    int idx = blockIdx.x * blockDim.x + threadIdx.x;
    const int vpr = rowlen / 4;
    if (idx >= nrows * vpr) return;
    const int r = idx / vpr, v = idx - r * vpr;
    const int b = perm[r];
    float4 f = *(const float4*)(src + (size_t)b * rowlen + v * 4);
    __half* d = dst + (size_t)r * rowlen + v * 4;
    *(__half2*)(d)     = __floats2half2_rn(f.x, f.y);
    *(__half2*)(d + 2) = __floats2half2_rn(f.z, f.w);
}

// caption -> fp16, sorted + time-major: dst[(t*B + r), :] = cap[perm[r], t, :]
__global__ void permcap_kernel(const float* __restrict__ cap, __half* __restrict__ dst,
                               const int* __restrict__ perm)
{
    int idx = blockIdx.x * blockDim.x + threadIdx.x;
    const int vpr = CD / 4;
    if (idx >= TT * BATCH * vpr) return;
    const int v = idx % vpr;
    const int row = idx / vpr;
    const int r = row & (BATCH - 1);
    const int t = row >> 11;
    const int b = perm[r];
    float4 f = *(const float4*)(cap + ((size_t)b * TT + t) * CD + v * 4);
    __half* d = dst + (size_t)row * CD + v * 4;
    *(__half2*)(d)     = __floats2half2_rn(f.x, f.y);
    *(__half2*)(d + 2) = __floats2half2_rn(f.z, f.w);
}

__global__ void zero_kernel(float* __restrict__ p, size_t n) {
    size_t i = (size_t)blockIdx.x * blockDim.x + threadIdx.x;
    if (i < n) p[i] = 0.0f;
}

__global__ void zero_state_kernel(float* __restrict__ f, __half* __restrict__ h, int n) {
    int i = blockIdx.x * blockDim.x + threadIdx.x;
    if (i < n) { f[i] = 0.0f; h[i] = __float2half(0.0f); }
}

__global__ void add_kernel(const float* __restrict__ a, const float* __restrict__ b,
                           float* __restrict__ c, int n) {
    int i = blockIdx.x * blockDim.x + threadIdx.x;
    if (i < n) c[i] = a[i] + b[i];
}

// ---------------- packed GRU elementwise kernels ----------------------------------
// GRU1 + attention over active prefix r < mt[t]. All sorted layouts.
__global__ void gru1_att_sorted(
    const float* __restrict__ gi1a,     // [T*B, 3CD] time-major sorted
    const float* __restrict__ gh1,      // [B, 3CD] sorted
    const float* __restrict__ caption,  // [B, T, CD] original order (fp32)
    const float* __restrict__ fvqs,     // [B, CD] sorted
    const int*   __restrict__ perm,
    const int*   __restrict__ mt,
    float* __restrict__ h1, __half* __restrict__ h1h,
    __half* __restrict__ atta,          // [T*B, CD] time-major sorted
    float* __restrict__ alphas,         // [B, T, CD] original order
    int t)
{
    int idx = blockIdx.x * blockDim.x + threadIdx.x;
    if (idx >= BATCH * CD) return;
    const int r = idx / CD, j = idx - r * CD;
    if (r >= mt[t]) return;                 // inactive: state held, alphas pre-zeroed

    const float* gi = gi1a + ((size_t)t * BATCH + r) * (3 * CD);
    const float* gh = gh1 + (size_t)r * (3 * CD);

    float hv = h1[idx];
    float rg = sigmf(gi[j]          + gh[j]);
    float zg = sigmf(gi[CD + j]     + gh[CD + j]);
    float ng = tanhf(gi[2 * CD + j] + rg * gh[2 * CD + j]);
    float h  = (1.0f - zg) * ng + zg * hv;
    h1[idx]  = h;
    h1h[idx] = __float2half(h);

    const int b = perm[r];
    float x = caption[((size_t)b * TT + t) * CD + j];
    float a = sigmf(h * fvqs[idx]) * x;
    atta[((size_t)t * BATCH + r) * CD + j] = __float2half(a);
    alphas[((size_t)b * TT + t) * CD + j] = a;
}

// GRU2 over active prefix; writes h2_all time-major sorted.
__global__ void gru2_sorted(
    const float* __restrict__ gi2a,     // [T*B, 3HD] time-major sorted
    const float* __restrict__ gh2,      // [B, 3HD] sorted
    const int*   __restrict__ mt,
    float* __restrict__ h2, __half* __restrict__ h2h,
    __half* __restrict__ h2ah,          // [T*B, HD] time-major sorted
    int t)
{
    int idx = blockIdx.x * blockDim.x + threadIdx.x;
    if (idx >= BATCH * HD) return;
    const int r = idx / HD, j = idx - r * HD;
    if (r >= mt[t]) return;

    const float* gi = gi2a + ((size_t)t * BATCH + r) * (3 * HD);
    const float* gh = gh2 + (size_t)r * (3 * HD);

    float hv = h2[idx];
    float rg = sigmf(gi[j]          + gh[j]);
    float zg = sigmf(gi[HD + j]     + gh[HD + j]);
    float ng = tanhf(gi[2 * HD + j] + rg * gh[2 * HD + j]);
    float h  = (1.0f - zg) * ng + zg * hv;
    h2[idx]  = h;
    __half hh = __float2half(h);
    h2h[idx] = hh;
    h2ah[((size_t)t * BATCH + r) * HD + j] = hh;
}

// out[b] = max(0, max_{t<len_b} leaky(y[t*B + rank_b])). Padded steps give 0 (len<20).
__global__ void maxreduce_out(
    const float* __restrict__ y,        // [T*B, HD] time-major sorted
    const int*   __restrict__ cap_len,
    const int*   __restrict__ rankof,
    float* __restrict__ out)
{
    int idx = blockIdx.x * blockDim.x + threadIdx.x;
    if (idx >= BATCH * HD) return;
    const int b = idx / HD, j = idx - b * HD;
    const int len = cap_len[b];
    const int r = rankof[b];
    float m = 0.0f;
    for (int t = 0; t < len; t++)
        m = fmaxf(m, leakyf(y[((size_t)t * BATCH + r) * HD + j]));
    out[idx] = m;
}

// ---------------- launch ------------------------------------------------------------
static inline dim3 gemm_grid(int M, int N) { return dim3(N / 128, M / 128); }

extern "C" void kernel_launch(void* const* d_in, const int* in_sizes, int n_in,
                              void* d_out, int out_size)
{
    const float* v       = (const float*)d_in[0];
    const float* q       = (const float*)d_in[1];
    const float* caption = (const float*)d_in[2];
    const int*   cap_len = (const int*)  d_in[3];
    const float* w_ih1   = (const float*)d_in[4];
    const float* w_hh1   = (const float*)d_in[5];
    const float* b_ih1   = (const float*)d_in[6];
    const float* b_hh1   = (const float*)d_in[7];
    const float* w_ih2   = (const float*)d_in[8];
    const float* w_hh2   = (const float*)d_in[9];
    const float* b_ih2   = (const float*)d_in[10];
    const float* b_hh2   = (const float*)d_in[11];
    const float* Wv      = (const float*)d_in[12];
    const float* Wq      = (const float*)d_in[13];
    const float* Wfc     = (const float*)d_in[14];

    float* out    = (float*)d_out;
    float* alphas = (float*)d_out + (size_t)BATCH * HD;

    float *fv, *fq, *fvq, *gi1a, *gh1, *gi2a, *gh2, *h1, *h2, *y;
    cudaGetSymbolAddress((void**)&fv,   g_fv);
    cudaGetSymbolAddress((void**)&fq,   g_fq);
    cudaGetSymbolAddress((void**)&fvq,  g_fvq);
    cudaGetSymbolAddress((void**)&gi1a, g_gi1a);
    cudaGetSymbolAddress((void**)&gh1,  g_gh1);
    cudaGetSymbolAddress((void**)&gi2a, g_gi2a);
    cudaGetSymbolAddress((void**)&gh2,  g_gh2);
    cudaGetSymbolAddress((void**)&h1,   g_h1);
    cudaGetSymbolAddress((void**)&h2,   g_h2);
    cudaGetSymbolAddress((void**)&y,    g_y);

    __half *c16s, *v16s, *q16s, *wih1h, *whh1h, *wih2h, *whh2h, *wvh, *wqh, *wfch;
    __half *h1h, *h2h, *atta, *h2ah;
    cudaGetSymbolAddress((void**)&c16s,  g_c16s);
    cudaGetSymbolAddress((void**)&v16s,  g_v16s);
    cudaGetSymbolAddress((void**)&q16s,  g_q16s);
    cudaGetSymbolAddress((void**)&wih1h, g_wih1h);
    cudaGetSymbolAddress((void**)&whh1h, g_whh1h);
    cudaGetSymbolAddress((void**)&wih2h, g_wih2h);
    cudaGetSymbolAddress((void**)&whh2h, g_whh2h);
    cudaGetSymbolAddress((void**)&wvh,   g_wvh);
    cudaGetSymbolAddress((void**)&wqh,   g_wqh);
    cudaGetSymbolAddress((void**)&wfch,  g_wfch);
    cudaGetSymbolAddress((void**)&h1h,   g_h1h);
    cudaGetSymbolAddress((void**)&h2h,   g_h2h);
    cudaGetSymbolAddress((void**)&atta,  g_atta);
    cudaGetSymbolAddress((void**)&h2ah,  g_h2ah);

    int *perm, *rankof, *mt;
    cudaGetSymbolAddress((void**)&perm,   g_perm);
    cudaGetSymbolAddress((void**)&rankof, g_rank);
    cudaGetSymbolAddress((void**)&mt,     g_mt);

    cudaFuncSetAttribute(h16_gemm_nt, cudaFuncAttributeMaxDynamicSharedMemorySize, SMEM_P);

    const int EW = 256;
    auto cvt = [&](const float* s, __half* d, int n) {
        f2h_kernel<<<(n / 4 + EW - 1) / EW, EW>>>(s, d, n);
    };

    // ---- sorting metadata ----
    rank_kernel<<<1, 1024>>>(cap_len, perm, rankof);
    mt_kernel<<<1, 32>>>(cap_len, mt);

    // ---- one-time conversions (weights plain; v/q/caption gathered into rank order)
    cvt(w_ih1, wih1h, 3 * CD * CD);
    cvt(w_hh1, whh1h, 3 * CD * CD);
    cvt(w_ih2, wih2h, 3 * HD * CD);
    cvt(w_hh2, whh2h, 3 * HD * HD);
    cvt(Wv,    wvh,   CD * VD);
    cvt(Wq,    wqh,   CD * QD);
    f2h_perm_kernel<<<(BATCH * (VD / 4) + EW - 1) / EW, EW>>>(v, v16s, perm, VD, BATCH);
    f2h_perm_kernel<<<(BATCH * (QD / 4) + EW - 1) / EW, EW>>>(q, q16s, perm, QD, BATCH);
    cvt(Wfc, wfch, HD * HD);
    permcap_kernel<<<(TT * BATCH * (CD / 4) + EW - 1) / EW, EW>>>(caption, c16s, perm);

    // ---- zero states + alphas ----
    zero_state_kernel<<<(BATCH * CD + EW - 1) / EW, EW>>>(h1, h1h, BATCH * CD);
    zero_state_kernel<<<(BATCH * HD + EW - 1) / EW, EW>>>(h2, h2h, BATCH * HD);
    {
        size_t n = (size_t)BATCH * TT * CD;
        zero_kernel<<<(unsigned)((n + EW - 1) / EW), EW>>>(alphas, n);
    }

    // ---- hoisted projections (sorted order) ----
    h16_gemm_nt<<<gemm_grid(BATCH, CD), 256, SMEM_P>>>(v16s, wvh, nullptr, fv,
                                                       BATCH, CD, VD, 1, nullptr, 0, 0);
    h16_gemm_nt<<<gemm_grid(BATCH, CD), 256, SMEM_P>>>(q16s, wqh, nullptr, fq,
                                                       BATCH, CD, QD, 1, nullptr, 0, 0);
    add_kernel<<<(BATCH * CD + EW - 1) / EW, EW>>>(fv, fq, fvq, BATCH * CD);

    // ---- hoisted GRU1 input GEMM (time-major, packed) ----
    h16_gemm_nt<<<gemm_grid(TT * BATCH, 3 * CD), 256, SMEM_P>>>(
        c16s, wih1h, b_ih1, gi1a, TT * BATCH, 3 * CD, CD, 0, mt, 0, 1);

    // ---- phase 1: h1 recurrence + attention ----
    for (int t = 0; t < TT; t++) {
        h16_gemm_nt<<<gemm_grid(BATCH, 3 * CD), 256, SMEM_P>>>(
            h1h, whh1h, b_hh1, gh1, BATCH, 3 * CD, CD, 0, mt, t, 0);
        gru1_att_sorted<<<(BATCH * CD + EW - 1) / EW, EW>>>(
            gi1a, gh1, caption, fvq, perm, mt, h1, h1h, atta, alphas, t);
    }

    // ---- phase 2: hoisted GRU2 input GEMM (time-major, packed) ----
    h16_gemm_nt<<<gemm_grid(TT * BATCH, 3 * HD), 256, SMEM_P>>>(
        atta, wih2h, b_ih2, gi2a, TT * BATCH, 3 * HD, CD, 0, mt, 0, 1);

    // ---- phase 3: h2 recurrence ----
    for (int t = 0; t < TT; t++) {
        h16_gemm_nt<<<gemm_grid(BATCH, 3 * HD), 256, SMEM_P>>>(
            h2h, whh2h, b_hh2, gh2, BATCH, 3 * HD, HD, 0, mt, t, 0);
        gru2_sorted<<<(BATCH * HD + EW - 1) / EW, EW>>>(
            gi2a, gh2, mt, h2, h2h, h2ah, t);
    }

    // ---- hoisted output GEMM (time-major, packed) + masked max ----
    h16_gemm_nt<<<gemm_grid(TT * BATCH, HD), 256, SMEM_P>>>(
        h2ah, wfch, nullptr, y, TT * BATCH, HD, HD, 0, mt, 0, 1);
    maxreduce_out<<<(BATCH * HD + EW - 1) / EW, EW>>>(y, cap_len, rankof, out);
}